// round 15
// baseline (speedup 1.0000x reference)
#include <cuda_runtime.h>
#include <cuda_fp16.h>
#include <cstdint>
#include <math.h>

#define B_ 16
#define I_ 512
#define O_ 512
#define T_ 256
#define L_ 4096
#define EPS_ 1e-8f

// ---------------------------------------------------------------------------
// Scratch
// ---------------------------------------------------------------------------
__device__ float g_s[B_ * I_];
__device__ float g_h1[B_ * T_];
__device__ float g_h2[B_ * T_];
__device__ __half g_bw[B_ * O_ * I_];      // 8 MB, demodulated weights fp16

// ---------------------------------------------------------------------------
// Helpers
// ---------------------------------------------------------------------------
__device__ __forceinline__ uint32_t smem_u32(const void* p) {
    uint32_t a;
    asm("{ .reg .u64 t; cvta.to.shared.u64 t, %1; cvt.u32.u64 %0, t; }" : "=r"(a) : "l"(p));
    return a;
}

#define LDSM4(r, addr) \
    asm volatile("ldmatrix.sync.aligned.m8n8.x4.shared.b16 {%0,%1,%2,%3}, [%4];" \
        : "=r"((r)[0]), "=r"((r)[1]), "=r"((r)[2]), "=r"((r)[3]) : "r"(addr))

#define LDSM4T(r, addr) \
    asm volatile("ldmatrix.sync.aligned.m8n8.x4.trans.shared.b16 {%0,%1,%2,%3}, [%4];" \
        : "=r"((r)[0]), "=r"((r)[1]), "=r"((r)[2]), "=r"((r)[3]) : "r"(addr))

#define MMA_F16(acc, a, b0, b1) \
    asm volatile("mma.sync.aligned.m16n8k16.row.col.f32.f16.f16.f32 " \
        "{%0,%1,%2,%3}, {%4,%5,%6,%7}, {%8,%9}, {%0,%1,%2,%3};" \
        : "+f"((acc)[0]), "+f"((acc)[1]), "+f"((acc)[2]), "+f"((acc)[3]) \
        : "r"((a)[0]), "r"((a)[1]), "r"((a)[2]), "r"((a)[3]), "r"(b0), "r"(b1))

#define CP_ASYNC16(smem_addr, gptr) \
    asm volatile("cp.async.cg.shared.global [%0], [%1], 16;" :: "r"(smem_addr), "l"(gptr))
#define CP_ASYNC_COMMIT() asm volatile("cp.async.commit_group;" ::: "memory")
#define CP_ASYNC_WAIT0()  asm volatile("cp.async.wait_group 0;" ::: "memory")

// ---------------------------------------------------------------------------
// Kernel 1: one linear layer, one warp per output. grid = (out_dim/8, B).
// ---------------------------------------------------------------------------
__global__ void lin_kernel(const float* __restrict__ in, const float* __restrict__ W,
                           const float* __restrict__ bias, float* __restrict__ out,
                           int out_dim, int do_silu, float add_const) {
    const int b = blockIdx.y;
    const int wid = threadIdx.x >> 5, lid = threadIdx.x & 31;
    const int j = blockIdx.x * 8 + wid;

    const float4* inv4 = (const float4*)(in + b * T_);
    const float4* w4   = (const float4*)(W + (size_t)j * T_);
    float acc = 0.0f;
    #pragma unroll
    for (int u = 0; u < T_ / 128; u++) {
        const float4 a = inv4[lid + u * 32];
        const float4 w = w4[lid + u * 32];
        acc += a.x * w.x + a.y * w.y + a.z * w.z + a.w * w.w;
    }
    #pragma unroll
    for (int off = 16; off > 0; off >>= 1) acc += __shfl_xor_sync(0xFFFFFFFFu, acc, off);
    if (lid == 0) {
        float z = acc + bias[j] + add_const;
        out[b * out_dim + j] = do_silu ? z / (1.0f + expf(-z)) : z;
    }
}

// ---------------------------------------------------------------------------
// Kernel 2: demodulation -> fp16 weights, K-major [b][o][i].
// One o-row per warp, s cached in registers, no smem/bar. grid (O/8, B).
// ---------------------------------------------------------------------------
__global__ __launch_bounds__(256, 6)
void demod_kernel(const float* __restrict__ weight) {
    const int b = blockIdx.y;
    const int wid = threadIdx.x >> 5, lid = threadIdx.x & 31;
    const int o = blockIdx.x * 8 + wid;

    const float4* s4p = (const float4*)(g_s + b * I_);
    const float4* w4p = (const float4*)(weight + (size_t)o * I_);

    float4 v[4];
    float ss = 0.0f;
    #pragma unroll
    for (int j = 0; j < 4; j++) {
        const float4 s = s4p[lid + j * 32];
        const float4 w = w4p[lid + j * 32];
        v[j].x = w.x * s.x; v[j].y = w.y * s.y;
        v[j].z = w.z * s.z; v[j].w = w.w * s.w;
        ss += v[j].x * v[j].x + v[j].y * v[j].y + v[j].z * v[j].z + v[j].w * v[j].w;
    }
    #pragma unroll
    for (int off = 16; off > 0; off >>= 1) ss += __shfl_xor_sync(0xFFFFFFFFu, ss, off);
    const float d = rsqrtf(ss + EPS_);

    uint2* dst = (uint2*)(g_bw + ((size_t)b * O_ + o) * I_);
    #pragma unroll
    for (int j = 0; j < 4; j++) {
        const __half2 p0 = __floats2half2_rn(v[j].x * d, v[j].y * d);
        const __half2 p1 = __floats2half2_rn(v[j].z * d, v[j].w * d);
        uint2 pk = { *(const uint32_t*)&p0, *(const uint32_t*)&p1 };
        dst[lid + j * 32] = pk;
    }
}

// ---------------------------------------------------------------------------
// Kernel 3: mma.sync fp16 batched GEMM  out[b,o,l] = sum_i bw[b,o,i]*x[b,i,l]
// Block tile 128(M) x 128(N), K chunks of 64 (8 iterations), 256 threads,
// warp tile 64x32, single fp16 A, fp32 accum, 2 SMEM stages.
// Per iteration: CP_A(c+1) | LDG Xh0(c+1) | MMA ks0-1 | STS h0 | LDG Xh1 |
//                MMA ks2-3 | STS h1 | wait | bar.   Half the syncs of K=32.
// ---------------------------------------------------------------------------
#define KCH 64
#define NCHUNK (I_ / KCH)                  // 8
#define PA 72                              // A pitch (fp16) -> 144 B rows
#define PX 136                             // X pitch (fp16) -> 272 B rows
#define A_BYTES (128 * PA * 2)             // 18432
#define X_BYTES (KCH * PX * 2)             // 17408
#define ST_A 0
#define ST_X (A_BYTES)
#define STAGE_SZ (A_BYTES + X_BYTES)       // 35840
#define SMEM_GEMM (2 * STAGE_SZ)           // 71680

__global__ __launch_bounds__(256, 2)
void gemm_mma(const float* __restrict__ x, float* __restrict__ out) {
    extern __shared__ __align__(16) char smem[];
    const uint32_t sb = smem_u32(smem);
    const int tid = threadIdx.x, lane = tid & 31, wid = tid >> 5;
    const int b = blockIdx.z, o0 = blockIdx.x * 128, l0 = blockIdx.y * 128;
    const int m0w = (wid & 1) * 64;    // warp m origin (2 warps in M)
    const int n0w = (wid >> 1) * 32;   // warp n origin (4 warps in N)

    const __half* AG = g_bw + ((size_t)(b * O_ + o0)) * I_;
    const float* xb = x + (size_t)b * I_ * L_;

    // A: 128 rows x 8 uint4/row = 1024 uint4; 4 cp.async per thread
    const int aRow = tid >> 1;                 // 0..127
    const int aCb  = (tid & 1) * 4;            // 0 or 4 (uint4 col base)
    // X half: 32 rows x 32 float4; row = xRow0 + 8r
    const int xRow0 = tid >> 5;                // 0..7
    const int xCol  = (tid & 31) * 4;

    float acc[4][4][4] = {};
    float4 px[4];

    const uint32_t frow = lane & 15, fc8 = (lane >> 4) * 8;

#define CP_A(k0, base) do { \
        const int koff = (k0); \
        _Pragma("unroll") \
        for (int q = 0; q < 4; q++) { \
            const uint32_t d = sb + (base) + ST_A + aRow * (PA * 2) + (aCb + q) * 16; \
            CP_ASYNC16(d, (const char*)(AG + (size_t)aRow * I_ + koff + (aCb + q) * 8)); \
        } \
        CP_ASYNC_COMMIT(); \
    } while (0)

#define LDG_XH(k0, h) do { \
        _Pragma("unroll") \
        for (int r = 0; r < 4; r++) \
            px[r] = *(const float4*)&xb[(size_t)((k0) + (h) + xRow0 + 8 * r) * L_ + l0 + xCol]; \
    } while (0)

#define STS_XH(base, h) do { \
        _Pragma("unroll") \
        for (int r = 0; r < 4; r++) { \
            const int row = (h) + xRow0 + 8 * r; \
            const __half hx = __float2half_rn(px[r].x), hy = __float2half_rn(px[r].y); \
            const __half hz = __float2half_rn(px[r].z), hw = __float2half_rn(px[r].w); \
            uint2 hv; \
            hv.x = (uint32_t)__half_as_ushort(hx) | ((uint32_t)__half_as_ushort(hy) << 16); \
            hv.y = (uint32_t)__half_as_ushort(hz) | ((uint32_t)__half_as_ushort(hw) << 16); \
            *(uint2*)(smem + (base) + ST_X + row * (PX * 2) + xCol * 2) = hv; \
        } \
    } while (0)

// MMA over k-steps [ks0, ks0+1] of the chunk in buffer `cur`
#define MMA_HALF(cur, ks0) do { \
        _Pragma("unroll") \
        for (int ks = (ks0); ks < (ks0) + 2; ks++) { \
            uint32_t ah[4][4], bh[2][4]; \
            _Pragma("unroll") \
            for (int mi = 0; mi < 4; mi++) { \
                const uint32_t ad = sb + (cur) + ST_A \
                    + (m0w + mi * 16 + frow) * (PA * 2) + (ks * 16 + fc8) * 2; \
                LDSM4(ah[mi], ad); \
            } \
            _Pragma("unroll") \
            for (int np = 0; np < 2; np++) { \
                const uint32_t bd = sb + (cur) + ST_X \
                    + (ks * 16 + frow) * (PX * 2) + (n0w + np * 16 + fc8) * 2; \
                LDSM4T(bh[np], bd); \
            } \
            _Pragma("unroll") \
            for (int mi = 0; mi < 4; mi++) { \
                _Pragma("unroll") \
                for (int nt = 0; nt < 4; nt++) { \
                    const int np = nt >> 1, hp = (nt & 1) * 2; \
                    MMA_F16(acc[mi][nt], ah[mi], bh[np][hp], bh[np][hp + 1]); \
                } \
            } \
        } \
    } while (0)

    // --- prologue: stage chunk 0 into buffer 0 ---
    CP_A(0, 0);
    LDG_XH(0, 0);  STS_XH(0, 0);
    LDG_XH(0, 32); STS_XH(0, 32);
    CP_ASYNC_WAIT0();
    __syncthreads();

    #pragma unroll 1
    for (int c = 0; c < NCHUNK; c++) {
        const uint32_t cur = (uint32_t)(c & 1) * STAGE_SZ;
        const uint32_t nxt = (uint32_t)(1 - (c & 1)) * STAGE_SZ;
        const bool has_next = (c + 1 < NCHUNK);

        if (has_next) {
            CP_A((c + 1) * KCH, nxt);       // async A for next chunk
            LDG_XH((c + 1) * KCH, 0);       // X next half0, hidden by MMA below
        }
        MMA_HALF(cur, 0);
        if (has_next) {
            STS_XH(nxt, 0);
            LDG_XH((c + 1) * KCH, 32);      // X next half1, hidden by MMA below
        }
        MMA_HALF(cur, 2);
        if (has_next) STS_XH(nxt, 32);

        CP_ASYNC_WAIT0();
        __syncthreads();
    }

    // epilogue
    const int g = lane >> 2, c2 = (lane & 3) * 2;
    #pragma unroll
    for (int mi = 0; mi < 4; mi++) {
        #pragma unroll
        for (int nt = 0; nt < 4; nt++) {
            const int o = o0 + m0w + mi * 16 + g;
            const int l = l0 + n0w + nt * 8 + c2;
            float* p = out + ((size_t)(b * O_ + o)) * L_ + l;
            float2 v0 = {acc[mi][nt][0], acc[mi][nt][1]};
            float2 v1 = {acc[mi][nt][2], acc[mi][nt][3]};
            *(float2*)p = v0;
            *(float2*)(p + 8 * L_) = v1;
        }
    }
#undef CP_A
#undef LDG_XH
#undef STS_XH
#undef MMA_HALF
}

// ---------------------------------------------------------------------------
extern "C" void kernel_launch(void* const* d_in, const int* in_sizes, int n_in,
                              void* d_out, int out_size) {
    const float* x      = (const float*)d_in[0];
    const float* t      = (const float*)d_in[1];
    const float* weight = (const float*)d_in[2];
    const float* W1     = (const float*)d_in[3];
    const float* b1     = (const float*)d_in[4];
    const float* W2     = (const float*)d_in[5];
    const float* b2     = (const float*)d_in[6];
    const float* W3     = (const float*)d_in[7];
    const float* b3     = (const float*)d_in[8];
    float* out = (float*)d_out;

    cudaFuncSetAttribute(gemm_mma, cudaFuncAttributeMaxDynamicSharedMemorySize, SMEM_GEMM);

    float* h1 = nullptr; float* h2 = nullptr; float* s = nullptr;
    cudaGetSymbolAddress((void**)&h1, g_h1);
    cudaGetSymbolAddress((void**)&h2, g_h2);
    cudaGetSymbolAddress((void**)&s,  g_s);

    lin_kernel<<<dim3(T_ / 8, B_), 256>>>(t,  W1, b1, h1, T_, 1, 0.0f);
    lin_kernel<<<dim3(T_ / 8, B_), 256>>>(h1, W2, b2, h2, T_, 1, 0.0f);
    lin_kernel<<<dim3(I_ / 8, B_), 256>>>(h2, W3, b3, s,  I_, 0, 1.0f);
    demod_kernel<<<dim3(O_ / 8, B_), 256>>>(weight);
    gemm_mma<<<dim3(O_ / 128, L_ / 128, B_), 256, SMEM_GEMM>>>(x, out);
}

// round 16
// speedup vs baseline: 1.0676x; 1.0676x over previous
#include <cuda_runtime.h>
#include <cuda_fp16.h>
#include <cstdint>
#include <math.h>

#define B_ 16
#define I_ 512
#define O_ 512
#define T_ 256
#define L_ 4096
#define EPS_ 1e-8f

// ---------------------------------------------------------------------------
// Scratch
// ---------------------------------------------------------------------------
__device__ float g_s[B_ * I_];
__device__ float g_h1[B_ * T_];
__device__ float g_h2[B_ * T_];
__device__ __half g_bw[B_ * O_ * I_];      // 8 MB, demodulated weights fp16

// ---------------------------------------------------------------------------
// Helpers
// ---------------------------------------------------------------------------
__device__ __forceinline__ uint32_t smem_u32(const void* p) {
    uint32_t a;
    asm("{ .reg .u64 t; cvta.to.shared.u64 t, %1; cvt.u32.u64 %0, t; }" : "=r"(a) : "l"(p));
    return a;
}

#define LDSM4(r, addr) \
    asm volatile("ldmatrix.sync.aligned.m8n8.x4.shared.b16 {%0,%1,%2,%3}, [%4];" \
        : "=r"((r)[0]), "=r"((r)[1]), "=r"((r)[2]), "=r"((r)[3]) : "r"(addr))

#define LDSM4T(r, addr) \
    asm volatile("ldmatrix.sync.aligned.m8n8.x4.trans.shared.b16 {%0,%1,%2,%3}, [%4];" \
        : "=r"((r)[0]), "=r"((r)[1]), "=r"((r)[2]), "=r"((r)[3]) : "r"(addr))

#define MMA_F16(acc, a, b0, b1) \
    asm volatile("mma.sync.aligned.m16n8k16.row.col.f32.f16.f16.f32 " \
        "{%0,%1,%2,%3}, {%4,%5,%6,%7}, {%8,%9}, {%0,%1,%2,%3};" \
        : "+f"((acc)[0]), "+f"((acc)[1]), "+f"((acc)[2]), "+f"((acc)[3]) \
        : "r"((a)[0]), "r"((a)[1]), "r"((a)[2]), "r"((a)[3]), "r"(b0), "r"(b1))

#define CP_ASYNC16(smem_addr, gptr) \
    asm volatile("cp.async.cg.shared.global [%0], [%1], 16;" :: "r"(smem_addr), "l"(gptr))
#define CP_ASYNC_COMMIT() asm volatile("cp.async.commit_group;" ::: "memory")
#define CP_ASYNC_WAIT0()  asm volatile("cp.async.wait_group 0;" ::: "memory")
#define CP_ASYNC_WAIT1()  asm volatile("cp.async.wait_group 1;" ::: "memory")

// ---------------------------------------------------------------------------
// Kernel 1: one linear layer, one warp per output. grid = (out_dim/8, B).
// ---------------------------------------------------------------------------
__global__ void lin_kernel(const float* __restrict__ in, const float* __restrict__ W,
                           const float* __restrict__ bias, float* __restrict__ out,
                           int out_dim, int do_silu, float add_const) {
    const int b = blockIdx.y;
    const int wid = threadIdx.x >> 5, lid = threadIdx.x & 31;
    const int j = blockIdx.x * 8 + wid;

    const float4* inv4 = (const float4*)(in + b * T_);
    const float4* w4   = (const float4*)(W + (size_t)j * T_);
    float acc = 0.0f;
    #pragma unroll
    for (int u = 0; u < T_ / 128; u++) {
        const float4 a = inv4[lid + u * 32];
        const float4 w = w4[lid + u * 32];
        acc += a.x * w.x + a.y * w.y + a.z * w.z + a.w * w.w;
    }
    #pragma unroll
    for (int off = 16; off > 0; off >>= 1) acc += __shfl_xor_sync(0xFFFFFFFFu, acc, off);
    if (lid == 0) {
        float z = acc + bias[j] + add_const;
        out[b * out_dim + j] = do_silu ? z / (1.0f + expf(-z)) : z;
    }
}

// ---------------------------------------------------------------------------
// Kernel 2: demodulation -> fp16 weights, K-major [b][o][i].
// Warp-per-o, 2 o's per warp, s cached in registers, no smem/bar.
// grid (O/16, B), block 256 (8 warps).
// ---------------------------------------------------------------------------
__global__ __launch_bounds__(256, 4)
void demod_kernel(const float* __restrict__ weight) {
    const int b = blockIdx.y;
    const int wid = threadIdx.x >> 5, lid = threadIdx.x & 31;
    const int o_base = blockIdx.x * 16 + wid * 2;

    // cache s-row slice: 4 float4 per lane (covers I=512 across the warp)
    const float4* s4p = (const float4*)(g_s + b * I_);
    float4 s4[4];
    #pragma unroll
    for (int j = 0; j < 4; j++) s4[j] = s4p[lid + j * 32];

    #pragma unroll
    for (int r = 0; r < 2; r++) {
        const int o = o_base + r;
        const float4* w4p = (const float4*)(weight + (size_t)o * I_);
        float4 v[4];
        float ss = 0.0f;
        #pragma unroll
        for (int j = 0; j < 4; j++) {
            const float4 w = w4p[lid + j * 32];
            v[j].x = w.x * s4[j].x; v[j].y = w.y * s4[j].y;
            v[j].z = w.z * s4[j].z; v[j].w = w.w * s4[j].w;
            ss += v[j].x * v[j].x + v[j].y * v[j].y + v[j].z * v[j].z + v[j].w * v[j].w;
        }
        #pragma unroll
        for (int off = 16; off > 0; off >>= 1) ss += __shfl_xor_sync(0xFFFFFFFFu, ss, off);
        const float d = rsqrtf(ss + EPS_);

        uint2* dst = (uint2*)(g_bw + ((size_t)b * O_ + o) * I_);
        #pragma unroll
        for (int j = 0; j < 4; j++) {
            const __half2 p0 = __floats2half2_rn(v[j].x * d, v[j].y * d);
            const __half2 p1 = __floats2half2_rn(v[j].z * d, v[j].w * d);
            uint2 pk = { *(const uint32_t*)&p0, *(const uint32_t*)&p1 };
            dst[lid + j * 32] = pk;
        }
    }
}

// ---------------------------------------------------------------------------
// Kernel 3: mma.sync fp16 batched GEMM  out[b,o,l] = sum_i bw[b,o,i]*x[b,i,l]
// Block tile 128(M) x 128(N), K chunks of 32, 256 threads (8 warps),
// warp tile 64x32, single fp16 A, fp32 accum. 3-stage cp.async pipeline.
// Grid: o-tile fastest so CTAs sharing an X tile run adjacently.
// (Best-measured configuration — round 11, 149.5 us.)
// ---------------------------------------------------------------------------
#define PA 40                      // A smem pitch (fp16)  -> 80 B rows
#define PX 136                     // X smem pitch (fp16)  -> 272 B rows
#define A_BYTES (128 * PA * 2)     // 10240
#define X_BYTES (32 * PX * 2)      // 8704
#define ST_A 0
#define ST_X (A_BYTES)
#define STAGE_SZ (A_BYTES + X_BYTES)           // 18944
#define NSTAGE 3
#define SMEM_GEMM (NSTAGE * STAGE_SZ)          // 56832
#define NCHUNK (I_ / 32)                       // 16

__global__ __launch_bounds__(256, 2)
void gemm_mma(const float* __restrict__ x, float* __restrict__ out) {
    extern __shared__ __align__(16) char smem[];
    const uint32_t sb = smem_u32(smem);
    const int tid = threadIdx.x, lane = tid & 31, wid = tid >> 5;
    const int b = blockIdx.z, o0 = blockIdx.x * 128, l0 = blockIdx.y * 128;
    const int m0w = (wid & 1) * 64;    // warp m origin (2 warps in M)
    const int n0w = (wid >> 1) * 32;   // warp n origin (4 warps in N)

    const __half* AG = g_bw + ((size_t)(b * O_ + o0)) * I_;
    const float* xb = x + (size_t)b * I_ * L_;

    const int aRow0 = tid >> 2, aC = tid & 3;     // A: pass r -> row aRow0 + 64*r
    const int xRow0 = tid >> 5;                   // X: pass r -> row xRow0 + 8*r
    const int xCol = (tid & 31) * 4;

    float acc[4][4][4] = {};
    float4 px[4];

    const uint32_t frow = lane & 15, fc8 = (lane >> 4) * 8;

#define CP_A(k0, base) do { \
        const int koff = (k0); \
        _Pragma("unroll") \
        for (int r = 0; r < 2; r++) { \
            const int row = aRow0 + 64 * r; \
            const uint32_t d = sb + (base) + ST_A + row * (PA * 2) + aC * 16; \
            CP_ASYNC16(d, (const char*)(AG + (size_t)row * I_ + koff + aC * 8)); \
        } \
        CP_ASYNC_COMMIT(); \
    } while (0)

#define LDG_X(k0) do { \
        _Pragma("unroll") \
        for (int r = 0; r < 4; r++) \
            px[r] = *(const float4*)&xb[(size_t)((k0) + xRow0 + 8 * r) * L_ + l0 + xCol]; \
    } while (0)

#define STS_X(base) do { \
        _Pragma("unroll") \
        for (int r = 0; r < 4; r++) { \
            const int row = xRow0 + 8 * r; \
            const __half hx = __float2half_rn(px[r].x), hy = __float2half_rn(px[r].y); \
            const __half hz = __float2half_rn(px[r].z), hw = __float2half_rn(px[r].w); \
            uint2 hv; \
            hv.x = (uint32_t)__half_as_ushort(hx) | ((uint32_t)__half_as_ushort(hy) << 16); \
            hv.y = (uint32_t)__half_as_ushort(hz) | ((uint32_t)__half_as_ushort(hw) << 16); \
            *(uint2*)(smem + (base) + ST_X + row * (PX * 2) + xCol * 2) = hv; \
        } \
    } while (0)

    // --- prologue ---
    LDG_X(0);
    STS_X(0 * STAGE_SZ);
    CP_A(0, 0 * STAGE_SZ);
    CP_A(32, 1 * STAGE_SZ);
    LDG_X(32);
    CP_ASYNC_WAIT1();      // A(0) landed (A(1) may still fly)
    __syncthreads();

    #pragma unroll 1
    for (int c = 0; c < NCHUNK; c++) {
        const uint32_t cur = (uint32_t)(c % NSTAGE) * STAGE_SZ;
        const uint32_t st1 = (uint32_t)((c + 1) % NSTAGE) * STAGE_SZ;
        const uint32_t st2 = (uint32_t)((c + 2) % NSTAGE) * STAGE_SZ;

        if (c + 1 < NCHUNK) STS_X(st1);            // px = X(c+1) from last iter
        if (c + 2 < NCHUNK) {
            CP_A((c + 2) * 32, st2);               // async, 2 ahead
            LDG_X((c + 2) * 32);                   // latency hidden by compute(c)
        }

        #pragma unroll
        for (int ks = 0; ks < 2; ks++) {
            uint32_t ah[4][4], bh[2][4];
            #pragma unroll
            for (int mi = 0; mi < 4; mi++) {
                const uint32_t ad = sb + cur + ST_A
                    + (m0w + mi * 16 + frow) * (PA * 2) + (ks * 16 + fc8) * 2;
                LDSM4(ah[mi], ad);
            }
            #pragma unroll
            for (int np = 0; np < 2; np++) {
                const uint32_t bd = sb + cur + ST_X
                    + (ks * 16 + frow) * (PX * 2) + (n0w + np * 16 + fc8) * 2;
                LDSM4T(bh[np], bd);
            }
            #pragma unroll
            for (int mi = 0; mi < 4; mi++) {
                #pragma unroll
                for (int nt = 0; nt < 4; nt++) {
                    const int np = nt >> 1, hp = (nt & 1) * 2;
                    MMA_F16(acc[mi][nt], ah[mi], bh[np][hp], bh[np][hp + 1]);
                }
            }
        }

        if (c + 2 < NCHUNK) CP_ASYNC_WAIT1();      // A(c+1) landed
        else                CP_ASYNC_WAIT0();
        __syncthreads();
    }

    // epilogue
    const int g = lane >> 2, c2 = (lane & 3) * 2;
    #pragma unroll
    for (int mi = 0; mi < 4; mi++) {
        #pragma unroll
        for (int nt = 0; nt < 4; nt++) {
            const int o = o0 + m0w + mi * 16 + g;
            const int l = l0 + n0w + nt * 8 + c2;
            float* p = out + ((size_t)(b * O_ + o)) * L_ + l;
            float2 v0 = {acc[mi][nt][0], acc[mi][nt][1]};
            float2 v1 = {acc[mi][nt][2], acc[mi][nt][3]};
            *(float2*)p = v0;
            *(float2*)(p + 8 * L_) = v1;
        }
    }
#undef CP_A
#undef LDG_X
#undef STS_X
}

// ---------------------------------------------------------------------------
extern "C" void kernel_launch(void* const* d_in, const int* in_sizes, int n_in,
                              void* d_out, int out_size) {
    const float* x      = (const float*)d_in[0];
    const float* t      = (const float*)d_in[1];
    const float* weight = (const float*)d_in[2];
    const float* W1     = (const float*)d_in[3];
    const float* b1     = (const float*)d_in[4];
    const float* W2     = (const float*)d_in[5];
    const float* b2     = (const float*)d_in[6];
    const float* W3     = (const float*)d_in[7];
    const float* b3     = (const float*)d_in[8];
    float* out = (float*)d_out;

    cudaFuncSetAttribute(gemm_mma, cudaFuncAttributeMaxDynamicSharedMemorySize, SMEM_GEMM);

    float* h1 = nullptr; float* h2 = nullptr; float* s = nullptr;
    cudaGetSymbolAddress((void**)&h1, g_h1);
    cudaGetSymbolAddress((void**)&h2, g_h2);
    cudaGetSymbolAddress((void**)&s,  g_s);

    lin_kernel<<<dim3(T_ / 8, B_), 256>>>(t,  W1, b1, h1, T_, 1, 0.0f);
    lin_kernel<<<dim3(T_ / 8, B_), 256>>>(h1, W2, b2, h2, T_, 1, 0.0f);
    lin_kernel<<<dim3(I_ / 8, B_), 256>>>(h2, W3, b3, s,  I_, 0, 1.0f);
    demod_kernel<<<dim3(O_ / 16, B_), 256>>>(weight);
    gemm_mma<<<dim3(O_ / 128, L_ / 128, B_), 256, SMEM_GEMM>>>(x, out);
}

// round 17
// speedup vs baseline: 1.1127x; 1.0423x over previous
#include <cuda_runtime.h>
#include <cuda_fp16.h>
#include <cstdint>
#include <math.h>

#define B_ 16
#define I_ 512
#define O_ 512
#define T_ 256
#define L_ 4096
#define EPS_ 1e-8f

// ---------------------------------------------------------------------------
// Scratch
// ---------------------------------------------------------------------------
__device__ float g_s[B_ * I_];
__device__ float g_h1[B_ * T_];
__device__ float g_h2[B_ * T_];
__device__ __half g_bw[B_ * O_ * I_];      // 8 MB, demodulated weights fp16

// ---------------------------------------------------------------------------
// Helpers
// ---------------------------------------------------------------------------
__device__ __forceinline__ uint32_t smem_u32(const void* p) {
    uint32_t a;
    asm("{ .reg .u64 t; cvta.to.shared.u64 t, %1; cvt.u32.u64 %0, t; }" : "=r"(a) : "l"(p));
    return a;
}

// Programmatic dependent launch controls (no-ops when launched without PDL)
#define GRID_TRIGGER() asm volatile("griddepcontrol.launch_dependents;" ::: "memory")
#define GRID_WAIT()    asm volatile("griddepcontrol.wait;" ::: "memory")

#define LDSM4(r, addr) \
    asm volatile("ldmatrix.sync.aligned.m8n8.x4.shared.b16 {%0,%1,%2,%3}, [%4];" \
        : "=r"((r)[0]), "=r"((r)[1]), "=r"((r)[2]), "=r"((r)[3]) : "r"(addr))

#define LDSM4T(r, addr) \
    asm volatile("ldmatrix.sync.aligned.m8n8.x4.trans.shared.b16 {%0,%1,%2,%3}, [%4];" \
        : "=r"((r)[0]), "=r"((r)[1]), "=r"((r)[2]), "=r"((r)[3]) : "r"(addr))

#define MMA_F16(acc, a, b0, b1) \
    asm volatile("mma.sync.aligned.m16n8k16.row.col.f32.f16.f16.f32 " \
        "{%0,%1,%2,%3}, {%4,%5,%6,%7}, {%8,%9}, {%0,%1,%2,%3};" \
        : "+f"((acc)[0]), "+f"((acc)[1]), "+f"((acc)[2]), "+f"((acc)[3]) \
        : "r"((a)[0]), "r"((a)[1]), "r"((a)[2]), "r"((a)[3]), "r"(b0), "r"(b1))

#define CP_ASYNC16(smem_addr, gptr) \
    asm volatile("cp.async.cg.shared.global [%0], [%1], 16;" :: "r"(smem_addr), "l"(gptr))
#define CP_ASYNC_COMMIT() asm volatile("cp.async.commit_group;" ::: "memory")
#define CP_ASYNC_WAIT0()  asm volatile("cp.async.wait_group 0;" ::: "memory")
#define CP_ASYNC_WAIT1()  asm volatile("cp.async.wait_group 1;" ::: "memory")

// ---------------------------------------------------------------------------
// Kernel 1: one linear layer, one warp per output. grid = (out_dim/8, B).
// ---------------------------------------------------------------------------
__global__ void lin_kernel(const float* __restrict__ in, const float* __restrict__ W,
                           const float* __restrict__ bias, float* __restrict__ out,
                           int out_dim, int do_silu, float add_const) {
    GRID_TRIGGER();          // let the next kernel in the chain start its ramp
    GRID_WAIT();             // predecessor's stores (our `in`) must be visible

    const int b = blockIdx.y;
    const int wid = threadIdx.x >> 5, lid = threadIdx.x & 31;
    const int j = blockIdx.x * 8 + wid;

    const float4* inv4 = (const float4*)(in + b * T_);
    const float4* w4   = (const float4*)(W + (size_t)j * T_);
    float acc = 0.0f;
    #pragma unroll
    for (int u = 0; u < T_ / 128; u++) {
        const float4 a = inv4[lid + u * 32];
        const float4 w = w4[lid + u * 32];
        acc += a.x * w.x + a.y * w.y + a.z * w.z + a.w * w.w;
    }
    #pragma unroll
    for (int off = 16; off > 0; off >>= 1) acc += __shfl_xor_sync(0xFFFFFFFFu, acc, off);
    if (lid == 0) {
        float z = acc + bias[j] + add_const;
        out[b * out_dim + j] = do_silu ? z / (1.0f + expf(-z)) : z;
    }
}

// ---------------------------------------------------------------------------
// Kernel 2: demodulation -> fp16 weights, K-major [b][o][i].
// One o-row per warp, s cached in registers, no smem/bar. grid (O/8, B).
// Triggers dependents at top so the GEMM can launch + run its X prologue
// concurrently with this kernel.
// ---------------------------------------------------------------------------
__global__ __launch_bounds__(256, 6)
void demod_kernel(const float* __restrict__ weight) {
    GRID_TRIGGER();          // GEMM may launch now; it waits before reading g_bw
    GRID_WAIT();             // lin3's g_s must be visible

    const int b = blockIdx.y;
    const int wid = threadIdx.x >> 5, lid = threadIdx.x & 31;
    const int o = blockIdx.x * 8 + wid;

    const float4* s4p = (const float4*)(g_s + b * I_);
    const float4* w4p = (const float4*)(weight + (size_t)o * I_);

    float4 v[4];
    float ss = 0.0f;
    #pragma unroll
    for (int j = 0; j < 4; j++) {
        const float4 s = s4p[lid + j * 32];
        const float4 w = w4p[lid + j * 32];
        v[j].x = w.x * s.x; v[j].y = w.y * s.y;
        v[j].z = w.z * s.z; v[j].w = w.w * s.w;
        ss += v[j].x * v[j].x + v[j].y * v[j].y + v[j].z * v[j].z + v[j].w * v[j].w;
    }
    #pragma unroll
    for (int off = 16; off > 0; off >>= 1) ss += __shfl_xor_sync(0xFFFFFFFFu, ss, off);
    const float d = rsqrtf(ss + EPS_);

    uint2* dst = (uint2*)(g_bw + ((size_t)b * O_ + o) * I_);
    #pragma unroll
    for (int j = 0; j < 4; j++) {
        const __half2 p0 = __floats2half2_rn(v[j].x * d, v[j].y * d);
        const __half2 p1 = __floats2half2_rn(v[j].z * d, v[j].w * d);
        uint2 pk = { *(const uint32_t*)&p0, *(const uint32_t*)&p1 };
        dst[lid + j * 32] = pk;
    }
}

// ---------------------------------------------------------------------------
// Kernel 3: mma.sync fp16 batched GEMM  out[b,o,l] = sum_i bw[b,o,i]*x[b,i,l]
// Block tile 128(M) x 128(N), K chunks of 32, 256 threads (8 warps),
// warp tile 64x32, single fp16 A, fp32 accum. 3-stage cp.async pipeline.
// PDL: the x-dependent prologue (LDG/STS of X(0), LDG X(1)) runs BEFORE the
// griddepcontrol.wait; only the g_bw reads (cp.async A) sit after it.
// Mainloop unchanged — at the fp16 mma.sync pipe wall.
// ---------------------------------------------------------------------------
#define PA 40                      // A smem pitch (fp16)  -> 80 B rows
#define PX 136                     // X smem pitch (fp16)  -> 272 B rows
#define A_BYTES (128 * PA * 2)     // 10240
#define X_BYTES (32 * PX * 2)      // 8704
#define ST_A 0
#define ST_X (A_BYTES)
#define STAGE_SZ (A_BYTES + X_BYTES)           // 18944
#define NSTAGE 3
#define SMEM_GEMM (NSTAGE * STAGE_SZ)          // 56832
#define NCHUNK (I_ / 32)                       // 16

__global__ __launch_bounds__(256, 2)
void gemm_mma(const float* __restrict__ x, float* __restrict__ out) {
    extern __shared__ __align__(16) char smem[];
    const uint32_t sb = smem_u32(smem);
    const int tid = threadIdx.x, lane = tid & 31, wid = tid >> 5;
    const int b = blockIdx.z, o0 = blockIdx.x * 128, l0 = blockIdx.y * 128;
    const int m0w = (wid & 1) * 64;    // warp m origin (2 warps in M)
    const int n0w = (wid >> 1) * 32;   // warp n origin (4 warps in N)

    const __half* AG = g_bw + ((size_t)(b * O_ + o0)) * I_;
    const float* xb = x + (size_t)b * I_ * L_;

    const int aRow0 = tid >> 2, aC = tid & 3;     // A: pass r -> row aRow0 + 64*r
    const int xRow0 = tid >> 5;                   // X: pass r -> row xRow0 + 8*r
    const int xCol = (tid & 31) * 4;

    float acc[4][4][4] = {};
    float4 px[4];

    const uint32_t frow = lane & 15, fc8 = (lane >> 4) * 8;

#define CP_A(k0, base) do { \
        const int koff = (k0); \
        _Pragma("unroll") \
        for (int r = 0; r < 2; r++) { \
            const int row = aRow0 + 64 * r; \
            const uint32_t d = sb + (base) + ST_A + row * (PA * 2) + aC * 16; \
            CP_ASYNC16(d, (const char*)(AG + (size_t)row * I_ + koff + aC * 8)); \
        } \
        CP_ASYNC_COMMIT(); \
    } while (0)

#define LDG_X(k0) do { \
        _Pragma("unroll") \
        for (int r = 0; r < 4; r++) \
            px[r] = *(const float4*)&xb[(size_t)((k0) + xRow0 + 8 * r) * L_ + l0 + xCol]; \
    } while (0)

#define STS_X(base) do { \
        _Pragma("unroll") \
        for (int r = 0; r < 4; r++) { \
            const int row = xRow0 + 8 * r; \
            const __half hx = __float2half_rn(px[r].x), hy = __float2half_rn(px[r].y); \
            const __half hz = __float2half_rn(px[r].z), hw = __float2half_rn(px[r].w); \
            uint2 hv; \
            hv.x = (uint32_t)__half_as_ushort(hx) | ((uint32_t)__half_as_ushort(hy) << 16); \
            hv.y = (uint32_t)__half_as_ushort(hz) | ((uint32_t)__half_as_ushort(hw) << 16); \
            *(uint2*)(smem + (base) + ST_X + row * (PX * 2) + xCol * 2) = hv; \
        } \
    } while (0)

    // --- prologue ---
    // x-dependent work first (independent of demod's g_bw):
    LDG_X(0);
    STS_X(0 * STAGE_SZ);
    LDG_X(32);             // in flight
    GRID_WAIT();           // demod's g_bw now visible
    CP_A(0, 0 * STAGE_SZ);
    CP_A(32, 1 * STAGE_SZ);
    CP_ASYNC_WAIT1();      // A(0) landed (A(1) may still fly)
    __syncthreads();

    #pragma unroll 1
    for (int c = 0; c < NCHUNK; c++) {
        const uint32_t cur = (uint32_t)(c % NSTAGE) * STAGE_SZ;
        const uint32_t st1 = (uint32_t)((c + 1) % NSTAGE) * STAGE_SZ;
        const uint32_t st2 = (uint32_t)((c + 2) % NSTAGE) * STAGE_SZ;

        if (c + 1 < NCHUNK) STS_X(st1);            // px = X(c+1) from last iter
        if (c + 2 < NCHUNK) {
            CP_A((c + 2) * 32, st2);               // async, 2 ahead
            LDG_X((c + 2) * 32);                   // latency hidden by compute(c)
        }

        #pragma unroll
        for (int ks = 0; ks < 2; ks++) {
            uint32_t ah[4][4], bh[2][4];
            #pragma unroll
            for (int mi = 0; mi < 4; mi++) {
                const uint32_t ad = sb + cur + ST_A
                    + (m0w + mi * 16 + frow) * (PA * 2) + (ks * 16 + fc8) * 2;
                LDSM4(ah[mi], ad);
            }
            #pragma unroll
            for (int np = 0; np < 2; np++) {
                const uint32_t bd = sb + cur + ST_X
                    + (ks * 16 + frow) * (PX * 2) + (n0w + np * 16 + fc8) * 2;
                LDSM4T(bh[np], bd);
            }
            #pragma unroll
            for (int mi = 0; mi < 4; mi++) {
                #pragma unroll
                for (int nt = 0; nt < 4; nt++) {
                    const int np = nt >> 1, hp = (nt & 1) * 2;
                    MMA_F16(acc[mi][nt], ah[mi], bh[np][hp], bh[np][hp + 1]);
                }
            }
        }

        if (c + 2 < NCHUNK) CP_ASYNC_WAIT1();      // A(c+1) landed
        else                CP_ASYNC_WAIT0();
        __syncthreads();
    }

    // epilogue
    const int g = lane >> 2, c2 = (lane & 3) * 2;
    #pragma unroll
    for (int mi = 0; mi < 4; mi++) {
        #pragma unroll
        for (int nt = 0; nt < 4; nt++) {
            const int o = o0 + m0w + mi * 16 + g;
            const int l = l0 + n0w + nt * 8 + c2;
            float* p = out + ((size_t)(b * O_ + o)) * L_ + l;
            float2 v0 = {acc[mi][nt][0], acc[mi][nt][1]};
            float2 v1 = {acc[mi][nt][2], acc[mi][nt][3]};
            *(float2*)p = v0;
            *(float2*)(p + 8 * L_) = v1;
        }
    }
#undef CP_A
#undef LDG_X
#undef STS_X
}

// ---------------------------------------------------------------------------
extern "C" void kernel_launch(void* const* d_in, const int* in_sizes, int n_in,
                              void* d_out, int out_size) {
    const float* x      = (const float*)d_in[0];
    const float* t      = (const float*)d_in[1];
    const float* weight = (const float*)d_in[2];
    const float* W1     = (const float*)d_in[3];
    const float* b1     = (const float*)d_in[4];
    const float* W2     = (const float*)d_in[5];
    const float* b2     = (const float*)d_in[6];
    const float* W3     = (const float*)d_in[7];
    const float* b3     = (const float*)d_in[8];
    float* out = (float*)d_out;

    cudaFuncSetAttribute(gemm_mma, cudaFuncAttributeMaxDynamicSharedMemorySize, SMEM_GEMM);

    float* h1 = nullptr; float* h2 = nullptr; float* s = nullptr;
    cudaGetSymbolAddress((void**)&h1, g_h1);
    cudaGetSymbolAddress((void**)&h2, g_h2);
    cudaGetSymbolAddress((void**)&s,  g_s);

    // PDL attribute: kernel may launch once its predecessor triggers
    // launch_dependents (falls back to completion order otherwise).
    cudaLaunchAttribute pdl[1];
    pdl[0].id = cudaLaunchAttributeProgrammaticStreamSerialization;
    pdl[0].val.programmaticStreamSerializationAllowed = 1;

    // lin1: normal launch (no predecessor)
    lin_kernel<<<dim3(T_ / 8, B_), 256>>>(t,  W1, b1, h1, T_, 1, 0.0f);

    {   // lin2
        cudaLaunchConfig_t cfg = {};
        cfg.gridDim = dim3(T_ / 8, B_); cfg.blockDim = dim3(256);
        cfg.stream = 0; cfg.attrs = pdl; cfg.numAttrs = 1;
        cudaLaunchKernelEx(&cfg, lin_kernel, (const float*)h1, W2, b2, (float*)h2, T_, 1, 0.0f);
    }
    {   // lin3
        cudaLaunchConfig_t cfg = {};
        cfg.gridDim = dim3(I_ / 8, B_); cfg.blockDim = dim3(256);
        cfg.stream = 0; cfg.attrs = pdl; cfg.numAttrs = 1;
        cudaLaunchKernelEx(&cfg, lin_kernel, (const float*)h2, W3, b3, (float*)s, I_, 0, 1.0f);
    }
    {   // demod
        cudaLaunchConfig_t cfg = {};
        cfg.gridDim = dim3(O_ / 8, B_); cfg.blockDim = dim3(256);
        cfg.stream = 0; cfg.attrs = pdl; cfg.numAttrs = 1;
        cudaLaunchKernelEx(&cfg, demod_kernel, weight);
    }
    {   // gemm — overlaps demod: X prologue before griddepcontrol.wait
        cudaLaunchConfig_t cfg = {};
        cfg.gridDim = dim3(O_ / 128, L_ / 128, B_); cfg.blockDim = dim3(256);
        cfg.dynamicSmemBytes = SMEM_GEMM;
        cfg.stream = 0; cfg.attrs = pdl; cfg.numAttrs = 1;
        cudaLaunchKernelEx(&cfg, gemm_mma, x, out);
    }
}